// round 9
// baseline (speedup 1.0000x reference)
#include <cuda_runtime.h>
#include <cuda_bf16.h>

// LandmarksLoss: mean((pred - true)^2), true = windowed 128x128 bell table.
//
// R8: latency-bound fix. Column-strip mapping: 224 threads/CTA, thread owns a
// fixed float4-column (w4 = tid%56) and walks 8 rows (stride 4 rows/iter), so
// the 4 bell-column predicates are loop-invariant and per-iter index math is
// one add + one compare. __launch_bounds__(224,4) gives ptxas ~73 regs so the
// 8 front-batched LDG.128 stay live (true MLP=8). Grid = n_bl*7 CTAs of 32
// rows each. Deterministic last-block final reduction.

#define H_DIM    224
#define W_DIM    224
#define ROWF4    (W_DIM / 4)           // 56 float4 per row
#define NF4_IMG  (H_DIM * ROWF4)       // 12544 float4 per image
#define SEGS     7                     // CTAs per image
#define SEG_ROWS (H_DIM / SEGS)        // 32 rows per CTA
#define SEG_F4   (SEG_ROWS * ROWF4)    // 1792 float4 per CTA
#define THREADS  224                   // 4 rows x 56 cols
#define ITERS    8                     // 8 x 4 rows = 32 rows
#define NWARP    (THREADS / 32)        // 7
#define MAX_PART 32768
#define DELTA    128
#define HALF     64

__device__ float        g_partials[MAX_PART];
__device__ unsigned int g_count = 0;

__device__ __forceinline__ float blockReduce(float v, float* s)
{
    #pragma unroll
    for (int off = 16; off > 0; off >>= 1)
        v += __shfl_down_sync(0xFFFFFFFFu, v, off);
    const int lane = threadIdx.x & 31;
    const int wid  = threadIdx.x >> 5;
    if (lane == 0) s[wid] = v;
    __syncthreads();
    if (wid == 0) {
        v = (lane < NWARP) ? s[lane] : 0.0f;
        #pragma unroll
        for (int off = 4; off > 0; off >>= 1)
            v += __shfl_down_sync(0xFFFFFFFFu, v, off);
    }
    return v;  // valid in thread 0
}

__global__ void __launch_bounds__(THREADS, 4)
landmarks_fused(const float* __restrict__ pred,
                const float* __restrict__ lm,
                const float* __restrict__ bell,
                float* __restrict__ out,
                int n_part, float inv_n)
{
    const int bl  = blockIdx.x / SEGS;
    const int seg = blockIdx.x % SEGS;
    const int tid = threadIdx.x;

    // Thread -> (starting row h0 in [0,4), fixed float4 column w4 in [0,56))
    const int h0 = tid / ROWF4;
    const int w4 = tid - h0 * ROWF4;

    const float4* img4 = reinterpret_cast<const float4*>(pred)
                       + (size_t)bl * NF4_IMG + seg * SEG_F4 + tid;

    // landmarks: [...,0] = y_r (cols), [...,1] = x_r (rows); jnp.round = rintf
    const int yr = (int)rintf(__ldg(&lm[2 * bl + 0]));
    const int xr = (int)rintf(__ldg(&lm[2 * bl + 1]));

    // Row index into bell for iter k: ix = ixb + 4k. Column: iy0..iy0+3 fixed.
    const int ixb = seg * SEG_ROWS + h0 + (HALF - xr);
    const int iy0 = 4 * w4 + (HALF - yr);

    // Loop-invariant column predicates.
    const bool c0 = ((unsigned)(iy0 + 0) < (unsigned)DELTA);
    const bool c1 = ((unsigned)(iy0 + 1) < (unsigned)DELTA);
    const bool c2 = ((unsigned)(iy0 + 2) < (unsigned)DELTA);
    const bool c3 = ((unsigned)(iy0 + 3) < (unsigned)DELTA);

    // Front-batch all 8 independent float4 loads (MLP = 8).
    float4 p[ITERS];
    #pragma unroll
    for (int k = 0; k < ITERS; ++k)
        p[k] = __ldg(img4 + k * (4 * ROWF4));

    float acc = 0.0f;

    #pragma unroll
    for (int k = 0; k < ITERS; ++k) {
        const int ix = ixb + 4 * k;
        const bool rok = ((unsigned)ix < (unsigned)DELTA);
        const float* rb = bell + (ix << 7) + iy0;

        float t0 = 0.f, t1 = 0.f, t2 = 0.f, t3 = 0.f;
        if (rok & c0) t0 = __ldg(rb + 0);
        if (rok & c1) t1 = __ldg(rb + 1);
        if (rok & c2) t2 = __ldg(rb + 2);
        if (rok & c3) t3 = __ldg(rb + 3);

        float d;
        d = p[k].x - t0; acc = fmaf(d, d, acc);
        d = p[k].y - t1; acc = fmaf(d, d, acc);
        d = p[k].z - t2; acc = fmaf(d, d, acc);
        d = p[k].w - t3; acc = fmaf(d, d, acc);
    }

    __shared__ float s[NWARP];
    const float bsum = blockReduce(acc, s);

    __shared__ bool amLast;
    if (tid == 0) {
        g_partials[blockIdx.x] = bsum;
        __threadfence();
        const unsigned prev = atomicAdd(&g_count, 1u);
        amLast = (prev == (unsigned)(gridDim.x - 1));
    }
    __syncthreads();

    if (amLast) {
        // Deterministic final reduction: fixed index order every run.
        float tot = 0.0f;
        for (int i = tid; i < n_part; i += THREADS)
            tot += __ldcg(&g_partials[i]);
        __syncthreads();   // reuse s[] safely
        const float t = blockReduce(tot, s);
        if (tid == 0) {
            out[0] = t * inv_n;
            g_count = 0;   // reset for next graph replay
        }
    }
}

extern "C" void kernel_launch(void* const* d_in, const int* in_sizes, int n_in,
                              void* d_out, int out_size)
{
    const float* pred = (const float*)d_in[0];  // (B, L, 224, 224)
    const float* lm   = (const float*)d_in[1];  // (B, L, 2)
    const float* bell = (const float*)d_in[2];  // (128, 128)
    float* out = (float*)d_out;

    const int n_bl  = in_sizes[1] / 2;          // B*L = 1088
    const int gridx = n_bl * SEGS;              // 7616 CTAs
    const float inv_n = 1.0f / ((float)n_bl * (float)(H_DIM * W_DIM));

    landmarks_fused<<<gridx, THREADS>>>(pred, lm, bell, out, gridx, inv_n);
}

// round 10
// speedup vs baseline: 1.0913x; 1.0913x over previous
#include <cuda_runtime.h>
#include <cuda_bf16.h>

// LandmarksLoss: mean((pred - true)^2), true = windowed 128x128 bell table.
//
// R10: R4's stage1 stream loop VERBATIM (the fastest measured stream: 36.7us,
// 5.9 TB/s) + fused deterministic last-block final reduction replacing the
// 5us stage2 launch. One CTA per (b,l) image, grid-stride float4 loop.

#define H_DIM     224
#define W_DIM     224
#define HW        (H_DIM * W_DIM)      // 50176
#define ROWF4     (W_DIM / 4)          // 56
#define NF4       (HW / 4)             // 12544
#define THREADS   256
#define NWARP     (THREADS / 32)
#define MAX_BL    4096
#define DELTA     128
#define HALF      64

__device__ float        g_partials[MAX_BL];
__device__ unsigned int g_count = 0;

__device__ __forceinline__ float blockReduce(float v, float* s)
{
    #pragma unroll
    for (int off = 16; off > 0; off >>= 1)
        v += __shfl_down_sync(0xFFFFFFFFu, v, off);
    const int lane = threadIdx.x & 31;
    const int wid  = threadIdx.x >> 5;
    if (lane == 0) s[wid] = v;
    __syncthreads();
    if (wid == 0) {
        v = (lane < NWARP) ? s[lane] : 0.0f;
        #pragma unroll
        for (int off = NWARP / 2; off > 0; off >>= 1)
            v += __shfl_down_sync(0xFFFFFFFFu, v, off);
    }
    return v;  // valid in thread 0
}

__global__ void __launch_bounds__(THREADS, 8)
landmarks_fused(const float* __restrict__ pred,
                const float* __restrict__ lm,
                const float* __restrict__ bell,
                float* __restrict__ out,
                int n_bl, float inv_n)
{
    const int bl = blockIdx.x;
    const float4* img = reinterpret_cast<const float4*>(pred + (size_t)bl * HW);

    // landmarks: [...,0] = y_r, [...,1] = x_r  (round-half-to-even = jnp.round)
    const int yr = (int)rintf(__ldg(&lm[2 * bl + 0]));
    const int xr = (int)rintf(__ldg(&lm[2 * bl + 1]));
    const int xoff = HALF - xr;   // ix = h + xoff  (bell row)
    const int yoff = HALF - yr;   // iy = w + yoff  (bell col)

    float acc = 0.0f;

    #pragma unroll 4
    for (int i = threadIdx.x; i < NF4; i += THREADS) {
        const float4 p = __ldg(&img[i]);

        const int h  = i / ROWF4;
        const int w0 = (i - h * ROWF4) * 4;

        const int ix = h + xoff;
        const bool rowok = ((unsigned)ix < (unsigned)DELTA);
        const int iy0 = w0 + yoff;
        const float* brow = bell + ix * DELTA;

        float t0 = 0.0f, t1 = 0.0f, t2 = 0.0f, t3 = 0.0f;
        if (rowok) {
            if ((unsigned)(iy0 + 0) < (unsigned)DELTA) t0 = __ldg(&brow[iy0 + 0]);
            if ((unsigned)(iy0 + 1) < (unsigned)DELTA) t1 = __ldg(&brow[iy0 + 1]);
            if ((unsigned)(iy0 + 2) < (unsigned)DELTA) t2 = __ldg(&brow[iy0 + 2]);
            if ((unsigned)(iy0 + 3) < (unsigned)DELTA) t3 = __ldg(&brow[iy0 + 3]);
        }

        const float d0 = p.x - t0;
        const float d1 = p.y - t1;
        const float d2 = p.z - t2;
        const float d3 = p.w - t3;
        acc = fmaf(d0, d0, acc);
        acc = fmaf(d1, d1, acc);
        acc = fmaf(d2, d2, acc);
        acc = fmaf(d3, d3, acc);
    }

    __shared__ float s[NWARP];
    const float bsum = blockReduce(acc, s);

    __shared__ bool amLast;
    if (threadIdx.x == 0) {
        g_partials[bl] = bsum;
        __threadfence();
        const unsigned prev = atomicAdd(&g_count, 1u);
        amLast = (prev == (unsigned)(gridDim.x - 1));
    }
    __syncthreads();

    if (amLast) {
        // Deterministic final reduction: fixed index order every run.
        float tot = 0.0f;
        for (int i = threadIdx.x; i < n_bl; i += THREADS)
            tot += __ldcg(&g_partials[i]);
        __syncthreads();   // reuse s[] safely
        const float t = blockReduce(tot, s);
        if (threadIdx.x == 0) {
            out[0] = t * inv_n;
            g_count = 0;   // reset for next graph replay
        }
    }
}

extern "C" void kernel_launch(void* const* d_in, const int* in_sizes, int n_in,
                              void* d_out, int out_size)
{
    const float* pred = (const float*)d_in[0];  // (B, L, 224, 224)
    const float* lm   = (const float*)d_in[1];  // (B, L, 2)
    const float* bell = (const float*)d_in[2];  // (128, 128)
    float* out = (float*)d_out;

    const int n_bl = in_sizes[1] / 2;           // B*L = 1088
    const float inv_n = 1.0f / ((float)n_bl * (float)HW);

    landmarks_fused<<<n_bl, THREADS>>>(pred, lm, bell, out, n_bl, inv_n);
}